// round 12
// baseline (speedup 1.0000x reference)
#include <cuda_runtime.h>
#include <math.h>

// Problem constants
#define NB 64
#define CC 384
#define LL 3136      // 56*56
#define MM 16
#define DD 384
#define L4 784       // LL/4 (float4 per lf row)

// Scratch (static device memory — no allocations)
__device__ float g_q[NB*MM*CC];     // scaled q, [n][m][c]
__device__ float g_p[NB*MM*LL];     // scores -> exp(scores - max), [n][m][l]
__device__ float g_isum[NB*MM];     // 1/rowsum
__device__ float g_f[NB*MM*CC];     // fusion (softmax-normalized), [n][m][c]

#define FMA4(A, s, V) { (A).x += (s)*(V).x; (A).y += (s)*(V).y; (A).z += (s)*(V).z; (A).w += (s)*(V).w; }

// ---------------------------------------------------------------------------
// Kernel 0: q[n,m,c] = scale * (sum_d x[n,m,d]*Wq[c,d] + bq[c])
// grid (12, 64): 32 c's per CTA, warp handles 4 c's sequentially, lanes span d.
// ---------------------------------------------------------------------------
__global__ __launch_bounds__(256) void k_q(const float* __restrict__ x,
                                           const float* __restrict__ Wq,
                                           const float* __restrict__ bq) {
    const int n    = blockIdx.y;
    const int cblk = blockIdx.x * 32;
    const int tid  = threadIdx.x;
    const int warp = tid >> 5, lane = tid & 31;

    __shared__ float x_s[MM*DD];
    for (int j = tid; j < MM*DD; j += 256) x_s[j] = x[n*MM*DD + j];
    __syncthreads();
    const float4* xs4 = reinterpret_cast<const float4*>(x_s);
    const float scale = 0.05103103630798287f;   // 384^-0.5

    for (int cc = 0; cc < 4; ++cc) {
        const int c = cblk + warp*4 + cc;
        const float4* wrow = reinterpret_cast<const float4*>(Wq + (size_t)c*DD);
        float acc[MM];
        #pragma unroll
        for (int m = 0; m < MM; ++m) acc[m] = 0.f;
        #pragma unroll
        for (int s = 0; s < 3; ++s) {
            const int d4 = s*32 + lane;
            const float4 wv = wrow[d4];
            #pragma unroll
            for (int m = 0; m < MM; ++m) {
                const float4 xv = xs4[m*96 + d4];
                acc[m] += wv.x*xv.x + wv.y*xv.y + wv.z*xv.z + wv.w*xv.w;
            }
        }
        #pragma unroll
        for (int m = 0; m < MM; ++m) {
            #pragma unroll
            for (int off = 16; off; off >>= 1)
                acc[m] += __shfl_xor_sync(0xffffffffu, acc[m], off);
        }
        if (lane == 0) {
            const float b = bq[c];
            #pragma unroll
            for (int m = 0; m < MM; ++m)
                g_q[n*MM*CC + m*CC + c] = scale * (acc[m] + b);
        }
    }
}

// ---------------------------------------------------------------------------
// Kernel A: scores[n,m,l] = sum_c q[n,m,c] * lf[n,c,l]   (scale folded into q)
// grid (4, 64): CTA covers 1024 l's; thread owns 4 consecutive l (float4) and
// all 16 m accumulators. lf streamed coalesced along l; q transposed in smem.
// ---------------------------------------------------------------------------
__global__ __launch_bounds__(256, 2) void k_scores(const float* __restrict__ lf) {
    const int n   = blockIdx.y;
    const int tid = threadIdx.x;
    const int l0  = blockIdx.x * 1024 + tid * 4;

    __shared__ float q_t[CC*MM];   // [c][m]
    for (int j = tid; j < MM*CC; j += 256) {
        const int m = j / CC, c = j % CC;
        q_t[c*MM + m] = g_q[n*MM*CC + j];
    }
    __syncthreads();
    if (l0 >= LL) return;

    const float4* qt4 = reinterpret_cast<const float4*>(q_t);
    float4 acc[MM];
    #pragma unroll
    for (int m = 0; m < MM; ++m) acc[m] = make_float4(0.f, 0.f, 0.f, 0.f);

    const float4* lfp = reinterpret_cast<const float4*>(lf) + (size_t)n*CC*L4 + (l0 >> 2);

    #pragma unroll 4
    for (int c = 0; c < CC; ++c) {
        const float4 v = lfp[(size_t)c * L4];   // lf[n, c, l0..l0+3]
        #pragma unroll
        for (int mq = 0; mq < 4; ++mq) {
            const float4 qv = qt4[c*4 + mq];    // q for m = 4mq..4mq+3 (broadcast)
            FMA4(acc[4*mq+0], qv.x, v);
            FMA4(acc[4*mq+1], qv.y, v);
            FMA4(acc[4*mq+2], qv.z, v);
            FMA4(acc[4*mq+3], qv.w, v);
        }
    }

    float4* pout = reinterpret_cast<float4*>(g_p) + (size_t)n*MM*L4 + (l0 >> 2);
    #pragma unroll
    for (int m = 0; m < MM; ++m) pout[(size_t)m * L4] = acc[m];
}

// ---------------------------------------------------------------------------
// Kernel B: row softmax over l (3136). Writes exp(s - max) in place, 1/sum out.
// grid 1024 (= n*16+m rows), 256 threads.
// ---------------------------------------------------------------------------
__global__ __launch_bounds__(256) void k_softmax() {
    const int row  = blockIdx.x;
    float4* p4     = reinterpret_cast<float4*>(g_p) + (size_t)row * L4;
    const int tid  = threadIdx.x;
    const int warp = tid >> 5, lane = tid & 31;
    __shared__ float red[8];

    float mx = -3.4e38f;
    for (int i = tid; i < L4; i += 256) {
        const float4 v = p4[i];
        mx = fmaxf(mx, fmaxf(fmaxf(v.x, v.y), fmaxf(v.z, v.w)));
    }
    #pragma unroll
    for (int off = 16; off; off >>= 1)
        mx = fmaxf(mx, __shfl_xor_sync(0xffffffffu, mx, off));
    if (lane == 0) red[warp] = mx;
    __syncthreads();
    float m_all = red[0];
    #pragma unroll
    for (int k = 1; k < 8; ++k) m_all = fmaxf(m_all, red[k]);
    __syncthreads();

    float s = 0.f;
    for (int i = tid; i < L4; i += 256) {
        float4 v = p4[i];
        v.x = expf(v.x - m_all); v.y = expf(v.y - m_all);
        v.z = expf(v.z - m_all); v.w = expf(v.w - m_all);
        p4[i] = v;
        s += (v.x + v.y) + (v.z + v.w);
    }
    #pragma unroll
    for (int off = 16; off; off >>= 1)
        s += __shfl_xor_sync(0xffffffffu, s, off);
    if (lane == 0) red[warp] = s;
    __syncthreads();
    if (tid == 0) {
        float tot = 0.f;
        #pragma unroll
        for (int k = 0; k < 8; ++k) tot += red[k];
        g_isum[row] = 1.0f / tot;
    }
}

// ---------------------------------------------------------------------------
// Kernel C: f[n,m,c] = isum[n,m] * sum_l p[n,m,l] * lf[n,c,l]
// grid (12, 64): CTA = 32 c's; warp owns 4 c rows, lanes span l (coalesced LDG),
// p staged in smem tiles of 512 l. 64 fp32 accumulators/thread, shuffle-reduced.
// ---------------------------------------------------------------------------
__global__ __launch_bounds__(256, 2) void k_fusion(const float* __restrict__ lf) {
    const int n    = blockIdx.y;
    const int tid  = threadIdx.x;
    const int warp = tid >> 5, lane = tid & 31;
    const int c0   = blockIdx.x * 32 + warp * 4;

    __shared__ float p_s[MM * 512];
    float4* ps4 = reinterpret_cast<float4*>(p_s);
    const float4* gp4 = reinterpret_cast<const float4*>(g_p) + (size_t)n*MM*L4;
    const float4* lf4 = reinterpret_cast<const float4*>(lf) + (size_t)n*CC*L4;

    float acc[64];
    #pragma unroll
    for (int i = 0; i < 64; ++i) acc[i] = 0.f;

    // 6 full tiles of 512 l's
    for (int t = 0; t < 6; ++t) {
        __syncthreads();
        #pragma unroll
        for (int k = 0; k < 8; ++k) {
            const int j = tid + k*256;          // 0..2047 (16 rows x 128 float4)
            const int r = j >> 7, col = j & 127;
            ps4[j] = gp4[(size_t)r*L4 + t*128 + col];
        }
        __syncthreads();
        #pragma unroll
        for (int s = 0; s < 4; ++s) {
            const int li = t*128 + s*32 + lane;
            const float4 v0 = lf4[(size_t)(c0+0)*L4 + li];
            const float4 v1 = lf4[(size_t)(c0+1)*L4 + li];
            const float4 v2 = lf4[(size_t)(c0+2)*L4 + li];
            const float4 v3 = lf4[(size_t)(c0+3)*L4 + li];
            #pragma unroll
            for (int m = 0; m < MM; ++m) {
                const float4 pv = ps4[m*128 + s*32 + lane];
                acc[m*4+0] += pv.x*v0.x + pv.y*v0.y + pv.z*v0.z + pv.w*v0.w;
                acc[m*4+1] += pv.x*v1.x + pv.y*v1.y + pv.z*v1.z + pv.w*v1.w;
                acc[m*4+2] += pv.x*v2.x + pv.y*v2.y + pv.z*v2.z + pv.w*v2.w;
                acc[m*4+3] += pv.x*v3.x + pv.y*v3.y + pv.z*v3.z + pv.w*v3.w;
            }
        }
    }

    // tail: l in [3072, 3136) -> 16 float4 per row
    __syncthreads();
    {
        const int r = tid >> 4, col = tid & 15;
        ps4[r*128 + col] = gp4[(size_t)r*L4 + 768 + col];
    }
    __syncthreads();
    if (lane < 16) {
        const int li = 768 + lane;
        const float4 v0 = lf4[(size_t)(c0+0)*L4 + li];
        const float4 v1 = lf4[(size_t)(c0+1)*L4 + li];
        const float4 v2 = lf4[(size_t)(c0+2)*L4 + li];
        const float4 v3 = lf4[(size_t)(c0+3)*L4 + li];
        #pragma unroll
        for (int m = 0; m < MM; ++m) {
            const float4 pv = ps4[m*128 + lane];
            acc[m*4+0] += pv.x*v0.x + pv.y*v0.y + pv.z*v0.z + pv.w*v0.w;
            acc[m*4+1] += pv.x*v1.x + pv.y*v1.y + pv.z*v1.z + pv.w*v1.w;
            acc[m*4+2] += pv.x*v2.x + pv.y*v2.y + pv.z*v2.z + pv.w*v2.w;
            acc[m*4+3] += pv.x*v3.x + pv.y*v3.y + pv.z*v3.z + pv.w*v3.w;
        }
    }

    // warp reduce each of the 64 accumulators
    #pragma unroll
    for (int i = 0; i < 64; ++i) {
        float v = acc[i];
        #pragma unroll
        for (int off = 16; off; off >>= 1)
            v += __shfl_xor_sync(0xffffffffu, v, off);
        acc[i] = v;
    }
    if (lane == 0) {
        #pragma unroll
        for (int m = 0; m < MM; ++m) {
            const float inv = g_isum[n*MM + m];
            #pragma unroll
            for (int cc = 0; cc < 4; ++cc)
                g_f[n*MM*CC + m*CC + c0 + cc] = acc[m*4+cc] * inv;
        }
    }
}

// ---------------------------------------------------------------------------
// Kernel D: out[n,m,d] = sum_c f[n,m,c]*Wu[d,c] + bu[d] + x[n,m,d]
// Same structure as k_q.
// ---------------------------------------------------------------------------
__global__ __launch_bounds__(256) void k_out(const float* __restrict__ x,
                                             const float* __restrict__ Wu,
                                             const float* __restrict__ bu,
                                             float* __restrict__ out) {
    const int n    = blockIdx.y;
    const int dblk = blockIdx.x * 32;
    const int tid  = threadIdx.x;
    const int warp = tid >> 5, lane = tid & 31;

    __shared__ float f_s[MM*CC];
    for (int j = tid; j < MM*CC; j += 256) f_s[j] = g_f[n*MM*CC + j];
    __syncthreads();
    const float4* fs4 = reinterpret_cast<const float4*>(f_s);

    for (int dd = 0; dd < 4; ++dd) {
        const int d = dblk + warp*4 + dd;
        const float4* wrow = reinterpret_cast<const float4*>(Wu + (size_t)d*CC);
        float acc[MM];
        #pragma unroll
        for (int m = 0; m < MM; ++m) acc[m] = 0.f;
        #pragma unroll
        for (int s = 0; s < 3; ++s) {
            const int c4 = s*32 + lane;
            const float4 wv = wrow[c4];
            #pragma unroll
            for (int m = 0; m < MM; ++m) {
                const float4 fv = fs4[m*96 + c4];
                acc[m] += wv.x*fv.x + wv.y*fv.y + wv.z*fv.z + wv.w*fv.w;
            }
        }
        #pragma unroll
        for (int m = 0; m < MM; ++m) {
            #pragma unroll
            for (int off = 16; off; off >>= 1)
                acc[m] += __shfl_xor_sync(0xffffffffu, acc[m], off);
        }
        if (lane == 0) {
            const float b = bu[d];
            #pragma unroll
            for (int m = 0; m < MM; ++m) {
                const int idx = n*MM*DD + m*DD + d;
                out[idx] = acc[m] + b + x[idx];
            }
        }
    }
}

// ---------------------------------------------------------------------------
extern "C" void kernel_launch(void* const* d_in, const int* in_sizes, int n_in,
                              void* d_out, int out_size) {
    const float* lf = (const float*)d_in[0];   // [64,384,56,56]
    const float* x  = (const float*)d_in[1];   // [64,16,384]
    const float* Wq = (const float*)d_in[2];   // [384,384]
    const float* bq = (const float*)d_in[3];   // [384]
    const float* Wu = (const float*)d_in[4];   // [384,384]
    const float* bu = (const float*)d_in[5];   // [384]
    float* out = (float*)d_out;                // [64,16,384]

    k_q      <<<dim3(12, 64), 256>>>(x, Wq, bq);
    k_scores <<<dim3(4,  64), 256>>>(lf);
    k_softmax<<<1024,         256>>>();
    k_fusion <<<dim3(12, 64), 256>>>(lf);
    k_out    <<<dim3(12, 64), 256>>>(x, Wu, bu, out);
}